// round 1
// baseline (speedup 1.0000x reference)
#include <cuda_runtime.h>
#include <cuda_bf16.h>
#include <math.h>

#define NNODES 250000
#define NEDGES 4000000
#define DIM 64
#define SCAN_B 1024
#define NSCANB ((NNODES + SCAN_B - 1) / SCAN_B)   // 245

// -------- scratch (device globals; allocation is forbidden) --------
__device__ int   g_deg[NNODES];
__device__ int   g_rowptr[NNODES + 1];
__device__ int   g_fill[NNODES];
__device__ int   g_col[NEDGES];
__device__ float g_dis[NNODES];
__device__ int   g_blocksum[NSCANB];
__device__ float g_bufA[(size_t)NNODES * DIM];
__device__ float g_bufB[(size_t)NNODES * DIM];

// -------- CSR build --------
__global__ void k_zero_deg() {
    int i = blockIdx.x * blockDim.x + threadIdx.x;
    if (i < NNODES) g_deg[i] = 0;
}

__global__ void k_count(const int* __restrict__ edge) {
    int e = blockIdx.x * blockDim.x + threadIdx.x;
    if (e < NEDGES) atomicAdd(&g_deg[edge[e]], 1);
}

// per-block exclusive scan of counts; block totals to g_blocksum
__global__ void k_scan1() {
    __shared__ int s[SCAN_B];
    int i = blockIdx.x * SCAN_B + threadIdx.x;
    int v = (i < NNODES) ? g_deg[i] : 0;
    s[threadIdx.x] = v;
    __syncthreads();
    for (int off = 1; off < SCAN_B; off <<= 1) {
        int t = (threadIdx.x >= off) ? s[threadIdx.x - off] : 0;
        __syncthreads();
        s[threadIdx.x] += t;
        __syncthreads();
    }
    if (i < NNODES) g_rowptr[i] = s[threadIdx.x] - v;   // local exclusive
    if (threadIdx.x == SCAN_B - 1) g_blocksum[blockIdx.x] = s[SCAN_B - 1];
}

// serial scan of 245 block sums (trivial)
__global__ void k_scan2() {
    int acc = 0;
    for (int b = 0; b < NSCANB; b++) {
        int v = g_blocksum[b];
        g_blocksum[b] = acc;
        acc += v;
    }
}

// add block offsets, produce fill cursors + dis
__global__ void k_scan3() {
    int i = blockIdx.x * SCAN_B + threadIdx.x;
    if (i < NNODES) {
        int v = g_rowptr[i] + g_blocksum[blockIdx.x];
        g_rowptr[i] = v;
        g_fill[i]   = v;
        g_dis[i]    = rsqrtf((float)(g_deg[i] + 1));   // +1 self loop; always > 0
    }
    if (i == 0) g_rowptr[NNODES] = NEDGES;
}

__global__ void k_fill(const int* __restrict__ edge) {
    int e = blockIdx.x * blockDim.x + threadIdx.x;
    if (e < NEDGES) {
        int r = edge[e];
        int slot = atomicAdd(&g_fill[r], 1);
        g_col[slot] = edge[NEDGES + e];
    }
}

// -------- SpMM: one warp per row, lane owns float2 slice of 64-dim row --------
// out[r] = dis[r] * ( dis[r]*fin[r] + sum_c dis[c]*fin[c] )
__global__ void k_spmm(const float* __restrict__ fin,
                       float* __restrict__ o1, int s1,
                       float* __restrict__ o2, int s2) {
    int warp = (blockIdx.x * blockDim.x + threadIdx.x) >> 5;
    if (warp >= NNODES) return;
    int lane = threadIdx.x & 31;
    int r = warp;

    int beg = g_rowptr[r];
    int end = g_rowptr[r + 1];
    float dr = g_dis[r];

    const float2* fin2 = (const float2*)fin;
    float2 self = __ldg(&fin2[(size_t)r * 32 + lane]);
    float2 acc;
    acc.x = dr * self.x;   // self loop contributes dis[r]*feat[r] to inner sum
    acc.y = dr * self.y;

    #pragma unroll 4
    for (int e = beg; e < end; e++) {
        int c   = __ldg(&g_col[e]);
        float dc = __ldg(&g_dis[c]);
        float2 f = __ldg(&fin2[(size_t)c * 32 + lane]);
        acc.x = fmaf(dc, f.x, acc.x);
        acc.y = fmaf(dc, f.y, acc.y);
    }
    acc.x *= dr;
    acc.y *= dr;

    ((float2*)(o1 + (size_t)r * s1))[lane] = acc;
    if (o2) ((float2*)(o2 + (size_t)r * s2))[lane] = acc;
}

extern "C" void kernel_launch(void* const* d_in, const int* in_sizes, int n_in,
                              void* d_out, int out_size) {
    const int*   edge = (const int*)d_in[0];    // [2, NEDGES] int32
    const float* emb  = (const float*)d_in[1];  // [NNODES, 64] f32
    float* out = (float*)d_out;                 // [N*3*64] all_feat + [N*64] final

    float *bufA, *bufB;
    cudaGetSymbolAddress((void**)&bufA, g_bufA);
    cudaGetSymbolAddress((void**)&bufB, g_bufB);

    const int T = 256;
    // ---- CSR build ----
    k_zero_deg<<<(NNODES + T - 1) / T, T>>>();
    k_count<<<(NEDGES + T - 1) / T, T>>>(edge);
    k_scan1<<<NSCANB, SCAN_B>>>();
    k_scan2<<<1, 1>>>();
    k_scan3<<<NSCANB, SCAN_B>>>();
    k_fill<<<(NEDGES + T - 1) / T, T>>>(edge);

    // ---- 3 propagation layers, epilogues fused into the output layout ----
    // all_feat perm (2,0,1): out[:,0,:]=L3, out[:,1,:]=L1, out[:,2,:]=L2; then final=L3
    int spmm_blocks = (NNODES * 32 + T - 1) / T;
    float* out_final = out + (size_t)NNODES * 3 * DIM;

    k_spmm<<<spmm_blocks, T>>>(emb,  bufA, DIM,      out + DIM,     3 * DIM);  // L1
    k_spmm<<<spmm_blocks, T>>>(bufA, bufB, DIM,      out + 2 * DIM, 3 * DIM);  // L2
    k_spmm<<<spmm_blocks, T>>>(bufB, out,  3 * DIM,  out_final,     DIM);      // L3
}

// round 2
// speedup vs baseline: 1.1501x; 1.1501x over previous
#include <cuda_runtime.h>
#include <cuda_fp16.h>
#include <math.h>

#define NNODES 250000
#define NEDGES 4000000
#define DIM 64
#define SCAN_B 1024
#define NSCANB ((NNODES + SCAN_B - 1) / SCAN_B)   // 245

// -------- scratch (device globals; allocation is forbidden) --------
__device__ int     g_deg[NNODES];
__device__ int     g_rowptr[NNODES + 1];
__device__ int     g_fill[NNODES];
__device__ int     g_col[NEDGES];
__device__ float   g_dis[NNODES];
__device__ int     g_blocksum[NSCANB];
// pre-scaled features s[r] = dis[r]*feat[r], stored fp16 (half2 per 2 dims)
__device__ __half2 g_sA[(size_t)NNODES * (DIM / 2)];
__device__ __half2 g_sB[(size_t)NNODES * (DIM / 2)];

// -------- CSR build --------
__global__ void k_zero_deg() {
    int i = blockIdx.x * blockDim.x + threadIdx.x;
    if (i < NNODES) g_deg[i] = 0;
}

__global__ void k_count(const int* __restrict__ edge) {
    int e = blockIdx.x * blockDim.x + threadIdx.x;
    if (e < NEDGES) atomicAdd(&g_deg[edge[e]], 1);
}

// per-block exclusive scan of counts; block totals to g_blocksum
__global__ void k_scan1() {
    __shared__ int s[SCAN_B];
    int i = blockIdx.x * SCAN_B + threadIdx.x;
    int v = (i < NNODES) ? g_deg[i] : 0;
    s[threadIdx.x] = v;
    __syncthreads();
    for (int off = 1; off < SCAN_B; off <<= 1) {
        int t = (threadIdx.x >= off) ? s[threadIdx.x - off] : 0;
        __syncthreads();
        s[threadIdx.x] += t;
        __syncthreads();
    }
    if (i < NNODES) g_rowptr[i] = s[threadIdx.x] - v;   // local exclusive
    if (threadIdx.x == SCAN_B - 1) g_blocksum[blockIdx.x] = s[SCAN_B - 1];
}

// parallel exclusive scan of the 245 block sums (1 block)
__global__ void k_scan2() {
    __shared__ int s[256];
    int i = threadIdx.x;
    int v = (i < NSCANB) ? g_blocksum[i] : 0;
    s[i] = v;
    __syncthreads();
    for (int off = 1; off < 256; off <<= 1) {
        int t = (i >= off) ? s[i - off] : 0;
        __syncthreads();
        s[i] += t;
        __syncthreads();
    }
    if (i < NSCANB) g_blocksum[i] = s[i] - v;
}

// add block offsets, produce fill cursors + dis
__global__ void k_scan3() {
    int i = blockIdx.x * SCAN_B + threadIdx.x;
    if (i < NNODES) {
        int v = g_rowptr[i] + g_blocksum[blockIdx.x];
        g_rowptr[i] = v;
        g_fill[i]   = v;
        g_dis[i]    = rsqrtf((float)(g_deg[i] + 1));   // +1 self loop; always > 0
    }
    if (i == 0) g_rowptr[NNODES] = NEDGES;
}

__global__ void k_fill(const int* __restrict__ edge) {
    int e = blockIdx.x * blockDim.x + threadIdx.x;
    if (e < NEDGES) {
        int r = edge[e];
        int slot = atomicAdd(&g_fill[r], 1);
        g_col[slot] = edge[NEDGES + e];
    }
}

// s0[r] = dis[r] * emb[r], fp16. One thread per half2 element.
__global__ void k_scale_emb(const float* __restrict__ emb) {
    int idx = blockIdx.x * blockDim.x + threadIdx.x;   // over N*32
    if (idx >= NNODES * (DIM / 2)) return;
    int r = idx >> 5;
    float d = g_dis[r];
    float2 v = ((const float2*)emb)[idx];
    g_sA[idx] = __floats2half2_rn(d * v.x, d * v.y);
}

// -------- SpMM on pre-scaled features --------
// inner[r] = s[r] + sum_c s[c]
// f32 out   = dis[r]   * inner
// s_next    = dis[r]^2 * inner   (fp16)
__global__ void k_spmm(const __half2* __restrict__ sin,
                       __half2* __restrict__ sout,            // nullable
                       float* __restrict__ o1, int s1,
                       float* __restrict__ o2, int s2) {      // o2 nullable
    int warp = (blockIdx.x * blockDim.x + threadIdx.x) >> 5;
    if (warp >= NNODES) return;
    int lane = threadIdx.x & 31;
    int r = warp;

    int beg = g_rowptr[r];
    int end = g_rowptr[r + 1];
    float dr = g_dis[r];

    float2 acc = __half22float2(__ldg(&sin[(size_t)r * 32 + lane]));  // self term

    #pragma unroll 8
    for (int e = beg; e < end; e++) {
        int c = __ldg(&g_col[e]);
        float2 f = __half22float2(__ldg(&sin[(size_t)c * 32 + lane]));
        acc.x += f.x;
        acc.y += f.y;
    }

    float2 outv;
    outv.x = dr * acc.x;
    outv.y = dr * acc.y;

    ((float2*)(o1 + (size_t)r * s1))[lane] = outv;
    if (o2) ((float2*)(o2 + (size_t)r * s2))[lane] = outv;
    if (sout) {
        float dr2 = dr * dr;
        sout[(size_t)r * 32 + lane] = __floats2half2_rn(dr2 * acc.x, dr2 * acc.y);
    }
}

extern "C" void kernel_launch(void* const* d_in, const int* in_sizes, int n_in,
                              void* d_out, int out_size) {
    const int*   edge = (const int*)d_in[0];    // [2, NEDGES] int32
    const float* emb  = (const float*)d_in[1];  // [NNODES, 64] f32
    float* out = (float*)d_out;                 // [N*3*64] all_feat + [N*64] final

    __half2 *sA, *sB;
    cudaGetSymbolAddress((void**)&sA, g_sA);
    cudaGetSymbolAddress((void**)&sB, g_sB);

    const int T = 256;
    // ---- CSR build ----
    k_zero_deg<<<(NNODES + T - 1) / T, T>>>();
    k_count<<<(NEDGES + T - 1) / T, T>>>(edge);
    k_scan1<<<NSCANB, SCAN_B>>>();
    k_scan2<<<1, 256>>>();
    k_scan3<<<NSCANB, SCAN_B>>>();
    k_fill<<<(NEDGES + T - 1) / T, T>>>(edge);
    k_scale_emb<<<(NNODES * 32 + T - 1) / T, T>>>(emb);

    // ---- 3 propagation layers ----
    // all_feat perm (2,0,1): out[:,0,:]=L3, out[:,1,:]=L1, out[:,2,:]=L2; then final=L3
    int spmm_blocks = (NNODES * 32 + T - 1) / T;
    float* out_final = out + (size_t)NNODES * 3 * DIM;

    k_spmm<<<spmm_blocks, T>>>(sA, sB, out + DIM,     3 * DIM, nullptr,  0);       // L1
    k_spmm<<<spmm_blocks, T>>>(sB, sA, out + 2 * DIM, 3 * DIM, nullptr,  0);       // L2
    k_spmm<<<spmm_blocks, T>>>(sA, nullptr, out,      3 * DIM, out_final, DIM);    // L3
}

// round 3
// speedup vs baseline: 1.1779x; 1.0242x over previous
#include <cuda_runtime.h>
#include <cuda_fp16.h>
#include <math.h>

#define NNODES 250000
#define NEDGES 4000000
#define DIM 64
#define SCAN_B 1024
#define NSCANB ((NNODES + SCAN_B - 1) / SCAN_B)   // 245

// -------- scratch (device globals; allocation is forbidden) --------
__device__ int     g_deg[NNODES];
__device__ int     g_rowptr[NNODES + 1];
__device__ int     g_fill[NNODES];
__device__ int     g_col[NEDGES];
__device__ float   g_dis[NNODES];
__device__ int     g_blocksum[NSCANB];
// pre-scaled features s[r] = dis[r]*feat[r], stored fp16 (half2 per 2 dims)
__device__ __half2 g_sA[(size_t)NNODES * (DIM / 2)];
__device__ __half2 g_sB[(size_t)NNODES * (DIM / 2)];

// -------- CSR build --------
__global__ void k_zero_deg() {
    int i = blockIdx.x * blockDim.x + threadIdx.x;
    if (i < NNODES) g_deg[i] = 0;
}

__global__ void k_count(const int* __restrict__ edge) {
    int e = blockIdx.x * blockDim.x + threadIdx.x;
    if (e < NEDGES) atomicAdd(&g_deg[edge[e]], 1);
}

// per-block exclusive scan of counts; block totals to g_blocksum
__global__ void k_scan1() {
    __shared__ int s[SCAN_B];
    int i = blockIdx.x * SCAN_B + threadIdx.x;
    int v = (i < NNODES) ? g_deg[i] : 0;
    s[threadIdx.x] = v;
    __syncthreads();
    for (int off = 1; off < SCAN_B; off <<= 1) {
        int t = (threadIdx.x >= off) ? s[threadIdx.x - off] : 0;
        __syncthreads();
        s[threadIdx.x] += t;
        __syncthreads();
    }
    if (i < NNODES) g_rowptr[i] = s[threadIdx.x] - v;   // local exclusive
    if (threadIdx.x == SCAN_B - 1) g_blocksum[blockIdx.x] = s[SCAN_B - 1];
}

// parallel exclusive scan of the 245 block sums (1 block)
__global__ void k_scan2() {
    __shared__ int s[256];
    int i = threadIdx.x;
    int v = (i < NSCANB) ? g_blocksum[i] : 0;
    s[i] = v;
    __syncthreads();
    for (int off = 1; off < 256; off <<= 1) {
        int t = (i >= off) ? s[i - off] : 0;
        __syncthreads();
        s[i] += t;
        __syncthreads();
    }
    if (i < NSCANB) g_blocksum[i] = s[i] - v;
}

// add block offsets, produce fill cursors + dis
__global__ void k_scan3() {
    int i = blockIdx.x * SCAN_B + threadIdx.x;
    if (i < NNODES) {
        int v = g_rowptr[i] + g_blocksum[blockIdx.x];
        g_rowptr[i] = v;
        g_fill[i]   = v;
        g_dis[i]    = rsqrtf((float)(g_deg[i] + 1));   // +1 self loop; always > 0
    }
    if (i == 0) g_rowptr[NNODES] = NEDGES;
}

__global__ void k_fill(const int* __restrict__ edge) {
    int e = blockIdx.x * blockDim.x + threadIdx.x;
    if (e < NEDGES) {
        int r = edge[e];
        int slot = atomicAdd(&g_fill[r], 1);
        g_col[slot] = edge[NEDGES + e];
    }
}

// s0[r] = dis[r] * emb[r], fp16. One thread per half2 element.
__global__ void k_scale_emb(const float* __restrict__ emb) {
    int idx = blockIdx.x * blockDim.x + threadIdx.x;   // over N*32
    if (idx >= NNODES * (DIM / 2)) return;
    int r = idx >> 5;
    float d = g_dis[r];
    float2 v = ((const float2*)emb)[idx];
    g_sA[idx] = __floats2half2_rn(d * v.x, d * v.y);
}

// -------- SpMM on pre-scaled features, 4-way MLP --------
// inner[r] = s[r] + sum_c s[c]
// f32 out   = dis[r]   * inner
// s_next    = dis[r]^2 * inner   (fp16)
__global__ void __launch_bounds__(256) k_spmm(
                       const __half2* __restrict__ sin,
                       __half2* __restrict__ sout,            // nullable
                       float* __restrict__ o1, int s1,
                       float* __restrict__ o2, int s2) {      // o2 nullable
    int warp = (blockIdx.x * blockDim.x + threadIdx.x) >> 5;
    if (warp >= NNODES) return;
    int lane = threadIdx.x & 31;
    int r = warp;

    int beg = g_rowptr[r];
    int end = g_rowptr[r + 1];
    float dr = g_dis[r];

    float2 acc = __half22float2(__ldg(&sin[(size_t)r * 32 + lane]));  // self term
    float2 acc2 = make_float2(0.f, 0.f);

    // 4-way unrolled body: 4 independent gathers in flight per warp
    int e = beg;
    int nfull = beg + ((end - beg) & ~3);
    for (; e < nfull; e += 4) {
        int c0 = __ldg(&g_col[e]);
        int c1 = __ldg(&g_col[e + 1]);
        int c2 = __ldg(&g_col[e + 2]);
        int c3 = __ldg(&g_col[e + 3]);
        __half2 h0 = __ldg(&sin[(size_t)c0 * 32 + lane]);
        __half2 h1 = __ldg(&sin[(size_t)c1 * 32 + lane]);
        __half2 h2 = __ldg(&sin[(size_t)c2 * 32 + lane]);
        __half2 h3 = __ldg(&sin[(size_t)c3 * 32 + lane]);
        float2 f0 = __half22float2(h0);
        float2 f1 = __half22float2(h1);
        float2 f2 = __half22float2(h2);
        float2 f3 = __half22float2(h3);
        acc.x  += f0.x + f1.x;
        acc.y  += f0.y + f1.y;
        acc2.x += f2.x + f3.x;
        acc2.y += f2.y + f3.y;
    }
    for (; e < end; e++) {
        int c = __ldg(&g_col[e]);
        float2 f = __half22float2(__ldg(&sin[(size_t)c * 32 + lane]));
        acc.x += f.x;
        acc.y += f.y;
    }
    acc.x += acc2.x;
    acc.y += acc2.y;

    float2 outv;
    outv.x = dr * acc.x;
    outv.y = dr * acc.y;

    ((float2*)(o1 + (size_t)r * s1))[lane] = outv;
    if (o2) ((float2*)(o2 + (size_t)r * s2))[lane] = outv;
    if (sout) {
        float dr2 = dr * dr;
        sout[(size_t)r * 32 + lane] = __floats2half2_rn(dr2 * acc.x, dr2 * acc.y);
    }
}

extern "C" void kernel_launch(void* const* d_in, const int* in_sizes, int n_in,
                              void* d_out, int out_size) {
    const int*   edge = (const int*)d_in[0];    // [2, NEDGES] int32
    const float* emb  = (const float*)d_in[1];  // [NNODES, 64] f32
    float* out = (float*)d_out;                 // [N*3*64] all_feat + [N*64] final

    __half2 *sA, *sB;
    cudaGetSymbolAddress((void**)&sA, g_sA);
    cudaGetSymbolAddress((void**)&sB, g_sB);

    const int T = 256;
    // ---- CSR build ----
    k_zero_deg<<<(NNODES + T - 1) / T, T>>>();
    k_count<<<(NEDGES + T - 1) / T, T>>>(edge);
    k_scan1<<<NSCANB, SCAN_B>>>();
    k_scan2<<<1, 256>>>();
    k_scan3<<<NSCANB, SCAN_B>>>();
    k_fill<<<(NEDGES + T - 1) / T, T>>>(edge);
    k_scale_emb<<<(NNODES * 32 + T - 1) / T, T>>>(emb);

    // ---- 3 propagation layers ----
    // all_feat perm (2,0,1): out[:,0,:]=L3, out[:,1,:]=L1, out[:,2,:]=L2; then final=L3
    int spmm_blocks = (NNODES * 32 + T - 1) / T;
    float* out_final = out + (size_t)NNODES * 3 * DIM;

    k_spmm<<<spmm_blocks, T>>>(sA, sB, out + DIM,     3 * DIM, nullptr,  0);       // L1
    k_spmm<<<spmm_blocks, T>>>(sB, sA, out + 2 * DIM, 3 * DIM, nullptr,  0);       // L2
    k_spmm<<<spmm_blocks, T>>>(sA, nullptr, out,      3 * DIM, out_final, DIM);    // L3
}

// round 4
// speedup vs baseline: 1.2543x; 1.0649x over previous
#include <cuda_runtime.h>
#include <cuda_fp16.h>
#include <math.h>

#define NNODES 250000
#define NEDGES 4000000
#define DIM 64
#define SCAN_B 1024
#define NSCANB ((NNODES + SCAN_B - 1) / SCAN_B)   // 245

// -------- scratch (device globals; allocation is forbidden) --------
__device__ int    g_deg[NNODES];
__device__ int    g_rowptr[NNODES + 1];
__device__ int    g_fill[NNODES];
__device__ int    g_col[NEDGES];
__device__ float  g_dis[NNODES];
__device__ int    g_blocksum[NSCANB];
// pre-scaled features s[r] = dis[r]*feat[r], fp16 packed: 8 float4 per row (128 B)
__device__ float4 g_sA[(size_t)NNODES * 8];
__device__ float4 g_sB[(size_t)NNODES * 8];

// -------- CSR build --------
__global__ void k_zero_deg() {
    int i = blockIdx.x * blockDim.x + threadIdx.x;
    if (i < NNODES) g_deg[i] = 0;
}

__global__ void k_count(const int* __restrict__ edge) {
    int e = blockIdx.x * blockDim.x + threadIdx.x;
    if (e < NEDGES) atomicAdd(&g_deg[edge[e]], 1);
}

__global__ void k_scan1() {
    __shared__ int s[SCAN_B];
    int i = blockIdx.x * SCAN_B + threadIdx.x;
    int v = (i < NNODES) ? g_deg[i] : 0;
    s[threadIdx.x] = v;
    __syncthreads();
    for (int off = 1; off < SCAN_B; off <<= 1) {
        int t = (threadIdx.x >= off) ? s[threadIdx.x - off] : 0;
        __syncthreads();
        s[threadIdx.x] += t;
        __syncthreads();
    }
    if (i < NNODES) g_rowptr[i] = s[threadIdx.x] - v;   // local exclusive
    if (threadIdx.x == SCAN_B - 1) g_blocksum[blockIdx.x] = s[SCAN_B - 1];
}

__global__ void k_scan2() {
    __shared__ int s[256];
    int i = threadIdx.x;
    int v = (i < NSCANB) ? g_blocksum[i] : 0;
    s[i] = v;
    __syncthreads();
    for (int off = 1; off < 256; off <<= 1) {
        int t = (i >= off) ? s[i - off] : 0;
        __syncthreads();
        s[i] += t;
        __syncthreads();
    }
    if (i < NSCANB) g_blocksum[i] = s[i] - v;
}

__global__ void k_scan3() {
    int i = blockIdx.x * SCAN_B + threadIdx.x;
    if (i < NNODES) {
        int v = g_rowptr[i] + g_blocksum[blockIdx.x];
        g_rowptr[i] = v;
        g_fill[i]   = v;
        g_dis[i]    = rsqrtf((float)(g_deg[i] + 1));   // +1 self loop; > 0
    }
    if (i == 0) g_rowptr[NNODES] = NEDGES;
}

__global__ void k_fill(const int* __restrict__ edge) {
    int e = blockIdx.x * blockDim.x + threadIdx.x;
    if (e < NEDGES) {
        int r = edge[e];
        int slot = atomicAdd(&g_fill[r], 1);
        g_col[slot] = edge[NEDGES + e];
    }
}

// s0[r] = dis[r] * emb[r], fp16 packed into float4 chunks (8 dims each)
__global__ void k_scale_emb(const float* __restrict__ emb) {
    int idx = blockIdx.x * blockDim.x + threadIdx.x;   // over N*8
    if (idx >= NNODES * 8) return;
    int r = idx >> 3;
    int chunk = idx & 7;
    float d = g_dis[r];
    const float4* e4 = (const float4*)emb;             // 16 float4 per row
    float4 a = e4[(size_t)r * 16 + chunk * 2];
    float4 b = e4[(size_t)r * 16 + chunk * 2 + 1];
    float4 outv;
    __half2* h = (__half2*)&outv;
    h[0] = __floats2half2_rn(d * a.x, d * a.y);
    h[1] = __floats2half2_rn(d * a.z, d * a.w);
    h[2] = __floats2half2_rn(d * b.x, d * b.y);
    h[3] = __floats2half2_rn(d * b.z, d * b.w);
    g_sA[idx] = outv;
}

__device__ __forceinline__ void add8(float* acc, float4 v) {
    __half2* h = (__half2*)&v;
    #pragma unroll
    for (int i = 0; i < 4; i++) {
        float2 f = __half22float2(h[i]);
        acc[2 * i]     += f.x;
        acc[2 * i + 1] += f.y;
    }
}

// -------- SpMM: 1 warp/row, 4 edges per LDG.128 --------
// lane group g = lane>>3 owns edge e+g; chunk = lane&7 owns dims [chunk*8, chunk*8+8)
__global__ void __launch_bounds__(256) k_spmm(
                       const float4* __restrict__ sin,
                       float4* __restrict__ sout,             // nullable
                       float* __restrict__ o1, int s1,
                       float* __restrict__ o2, int s2) {      // o2 nullable
    int warp = (blockIdx.x * blockDim.x + threadIdx.x) >> 5;
    if (warp >= NNODES) return;
    int lane  = threadIdx.x & 31;
    int g     = lane >> 3;
    int chunk = lane & 7;
    int r = warp;

    int beg = g_rowptr[r];
    int end = g_rowptr[r + 1];
    float dr = g_dis[r];

    float acc[8];
    #pragma unroll
    for (int i = 0; i < 8; i++) acc[i] = 0.f;
    if (g == 3) add8(acc, __ldg(&sin[(size_t)r * 8 + chunk]));   // self term (counted once)

    int e = beg;
    // main: 8 edges per iteration, 2 independent LDG.128 per thread
    for (; e + 8 <= end; e += 8) {
        int c0 = __ldg(&g_col[e + g]);
        int c1 = __ldg(&g_col[e + 4 + g]);
        float4 v0 = __ldg(&sin[(size_t)c0 * 8 + chunk]);
        float4 v1 = __ldg(&sin[(size_t)c1 * 8 + chunk]);
        add8(acc, v0);
        add8(acc, v1);
    }
    // tail: up to 7 edges, 4 per iteration with validity masking
    for (; e < end; e += 4) {
        int idx = e + g;
        bool valid = idx < end;
        int c = valid ? __ldg(&g_col[idx]) : r;
        float4 v = __ldg(&sin[(size_t)c * 8 + chunk]);
        if (valid) add8(acc, v);
    }

    // reduce across the 4 lane groups (lanes {l, l^8, l^16, l^24})
    #pragma unroll
    for (int i = 0; i < 8; i++) {
        acc[i] += __shfl_xor_sync(0xffffffffu, acc[i], 8);
        acc[i] += __shfl_xor_sync(0xffffffffu, acc[i], 16);
    }

    float outv[8];
    #pragma unroll
    for (int i = 0; i < 8; i++) outv[i] = dr * acc[i];

    // split the epilogue stores across lane groups (no redundant traffic)
    if (g == 0) {
        float4* dst = (float4*)(o1 + (size_t)r * s1 + chunk * 8);
        dst[0] = make_float4(outv[0], outv[1], outv[2], outv[3]);
        dst[1] = make_float4(outv[4], outv[5], outv[6], outv[7]);
    } else if (g == 1 && o2) {
        float4* dst = (float4*)(o2 + (size_t)r * s2 + chunk * 8);
        dst[0] = make_float4(outv[0], outv[1], outv[2], outv[3]);
        dst[1] = make_float4(outv[4], outv[5], outv[6], outv[7]);
    } else if (g == 2 && sout) {
        float dr2 = dr * dr;
        float4 packed;
        __half2* h = (__half2*)&packed;
        h[0] = __floats2half2_rn(dr2 * acc[0], dr2 * acc[1]);
        h[1] = __floats2half2_rn(dr2 * acc[2], dr2 * acc[3]);
        h[2] = __floats2half2_rn(dr2 * acc[4], dr2 * acc[5]);
        h[3] = __floats2half2_rn(dr2 * acc[6], dr2 * acc[7]);
        sout[(size_t)r * 8 + chunk] = packed;
    }
}

extern "C" void kernel_launch(void* const* d_in, const int* in_sizes, int n_in,
                              void* d_out, int out_size) {
    const int*   edge = (const int*)d_in[0];    // [2, NEDGES] int32
    const float* emb  = (const float*)d_in[1];  // [NNODES, 64] f32
    float* out = (float*)d_out;                 // [N*3*64] all_feat + [N*64] final

    float4 *sA, *sB;
    cudaGetSymbolAddress((void**)&sA, g_sA);
    cudaGetSymbolAddress((void**)&sB, g_sB);

    const int T = 256;
    // ---- CSR build ----
    k_zero_deg<<<(NNODES + T - 1) / T, T>>>();
    k_count<<<(NEDGES + T - 1) / T, T>>>(edge);
    k_scan1<<<NSCANB, SCAN_B>>>();
    k_scan2<<<1, 256>>>();
    k_scan3<<<NSCANB, SCAN_B>>>();
    k_fill<<<(NEDGES + T - 1) / T, T>>>(edge);
    k_scale_emb<<<(NNODES * 8 + T - 1) / T, T>>>(emb);

    // ---- 3 propagation layers ----
    // all_feat perm (2,0,1): out[:,0,:]=L3, out[:,1,:]=L1, out[:,2,:]=L2; then final=L3
    int spmm_blocks = (NNODES * 32 + T - 1) / T;
    float* out_final = out + (size_t)NNODES * 3 * DIM;

    k_spmm<<<spmm_blocks, T>>>(sA, sB, out + DIM,     3 * DIM, nullptr,  0);       // L1
    k_spmm<<<spmm_blocks, T>>>(sB, sA, out + 2 * DIM, 3 * DIM, nullptr,  0);       // L2
    k_spmm<<<spmm_blocks, T>>>(sA, nullptr, out,      3 * DIM, out_final, DIM);    // L3
}

// round 5
// speedup vs baseline: 1.2618x; 1.0060x over previous
#include <cuda_runtime.h>
#include <cuda_fp16.h>
#include <math.h>

#define NNODES 250000
#define NEDGES 4000000
#define DIM 64
#define SCAN_B 1024
#define NSCANB ((NNODES + SCAN_B - 1) / SCAN_B)   // 245

// -------- scratch (device globals; allocation is forbidden) --------
__device__ int    g_deg[NNODES];
__device__ int    g_rowptr[NNODES + 1];
__device__ int    g_fill[NNODES];
__device__ int    g_col[NEDGES];
__device__ float  g_dis[NNODES];
__device__ int    g_blocksum[NSCANB];
// pre-scaled features s[r] = dis[r]*feat[r], fp16 packed: 8 float4 per row (128 B)
__device__ float4 g_sA[(size_t)NNODES * 8];
__device__ float4 g_sB[(size_t)NNODES * 8];

// -------- CSR build --------
__global__ void k_zero_deg() {
    int i = blockIdx.x * blockDim.x + threadIdx.x;
    if (i < NNODES) g_deg[i] = 0;
}

__global__ void k_count(const int* __restrict__ edge) {
    int e = blockIdx.x * blockDim.x + threadIdx.x;
    if (e < NEDGES) atomicAdd(&g_deg[__ldcs(&edge[e])], 1);
}

// warp-shuffle based block scan (exclusive), block totals to g_blocksum
__global__ void k_scan1() {
    __shared__ int warp_tot[SCAN_B / 32];
    int i = blockIdx.x * SCAN_B + threadIdx.x;
    int lane = threadIdx.x & 31;
    int wid  = threadIdx.x >> 5;
    int v = (i < NNODES) ? g_deg[i] : 0;

    // inclusive warp scan
    int x = v;
    #pragma unroll
    for (int off = 1; off < 32; off <<= 1) {
        int t = __shfl_up_sync(0xffffffffu, x, off);
        if (lane >= off) x += t;
    }
    if (lane == 31) warp_tot[wid] = x;
    __syncthreads();

    // scan the 32 warp totals with warp 0
    if (wid == 0) {
        int wt = warp_tot[lane];
        int y = wt;
        #pragma unroll
        for (int off = 1; off < 32; off <<= 1) {
            int t = __shfl_up_sync(0xffffffffu, y, off);
            if (lane >= off) y += t;
        }
        warp_tot[lane] = y - wt;   // exclusive
        if (lane == 31) g_blocksum[blockIdx.x] = y;
    }
    __syncthreads();

    if (i < NNODES) g_rowptr[i] = x - v + warp_tot[wid];   // block-local exclusive
}

// parallel exclusive scan of the 245 block sums (1 block)
__global__ void k_scan2() {
    __shared__ int s[256];
    int i = threadIdx.x;
    int v = (i < NSCANB) ? g_blocksum[i] : 0;
    s[i] = v;
    __syncthreads();
    for (int off = 1; off < 256; off <<= 1) {
        int t = (i >= off) ? s[i - off] : 0;
        __syncthreads();
        s[i] += t;
        __syncthreads();
    }
    if (i < NSCANB) g_blocksum[i] = s[i] - v;
}

__global__ void k_scan3() {
    int i = blockIdx.x * SCAN_B + threadIdx.x;
    if (i < NNODES) {
        int v = g_rowptr[i] + g_blocksum[blockIdx.x];
        g_rowptr[i] = v;
        g_fill[i]   = v;
        g_dis[i]    = rsqrtf((float)(g_deg[i] + 1));   // +1 self loop; > 0
    }
    if (i == 0) g_rowptr[NNODES] = NEDGES;
}

__global__ void k_fill(const int* __restrict__ edge) {
    int e = blockIdx.x * blockDim.x + threadIdx.x;
    if (e < NEDGES) {
        int r = __ldcs(&edge[e]);
        int c = __ldcs(&edge[NEDGES + e]);
        int slot = atomicAdd(&g_fill[r], 1);
        g_col[slot] = c;
    }
}

// s0[r] = dis[r] * emb[r], fp16 packed into float4 chunks (8 dims each)
__global__ void k_scale_emb(const float* __restrict__ emb) {
    int idx = blockIdx.x * blockDim.x + threadIdx.x;   // over N*8
    if (idx >= NNODES * 8) return;
    int r = idx >> 3;
    int chunk = idx & 7;
    float d = g_dis[r];
    const float4* e4 = (const float4*)emb;             // 16 float4 per row
    float4 a = __ldcs(&e4[(size_t)r * 16 + chunk * 2]);
    float4 b = __ldcs(&e4[(size_t)r * 16 + chunk * 2 + 1]);
    float4 outv;
    __half2* h = (__half2*)&outv;
    h[0] = __floats2half2_rn(d * a.x, d * a.y);
    h[1] = __floats2half2_rn(d * a.z, d * a.w);
    h[2] = __floats2half2_rn(d * b.x, d * b.y);
    h[3] = __floats2half2_rn(d * b.z, d * b.w);
    g_sA[idx] = outv;
}

__device__ __forceinline__ void add8(float* acc, float4 v) {
    __half2* h = (__half2*)&v;
    #pragma unroll
    for (int i = 0; i < 4; i++) {
        float2 f = __half22float2(h[i]);
        acc[2 * i]     += f.x;
        acc[2 * i + 1] += f.y;
    }
}

// -------- SpMM: 1 warp/row, 4 edges per LDG.128 --------
// lane group g = lane>>3 owns edge e+g; chunk = lane&7 owns dims [chunk*8, chunk*8+8)
// f32 outputs stored with streaming hint (never re-read) so the fp16 gather
// table stays L2-resident.
__global__ void __launch_bounds__(256) k_spmm(
                       const float4* __restrict__ sin,
                       float4* __restrict__ sout,             // nullable
                       float* __restrict__ o1, int s1,
                       float* __restrict__ o2, int s2) {      // o2 nullable
    int warp = (blockIdx.x * blockDim.x + threadIdx.x) >> 5;
    if (warp >= NNODES) return;
    int lane  = threadIdx.x & 31;
    int g     = lane >> 3;
    int chunk = lane & 7;
    int r = warp;

    int beg = g_rowptr[r];
    int end = g_rowptr[r + 1];
    float dr = g_dis[r];

    float acc[8];
    #pragma unroll
    for (int i = 0; i < 8; i++) acc[i] = 0.f;
    if (g == 3) add8(acc, __ldg(&sin[(size_t)r * 8 + chunk]));   // self term (once)

    int e = beg;
    // main: 8 edges per iteration, 2 independent LDG.128 per thread
    for (; e + 8 <= end; e += 8) {
        int c0 = __ldcs(&g_col[e + g]);
        int c1 = __ldcs(&g_col[e + 4 + g]);
        float4 v0 = __ldg(&sin[(size_t)c0 * 8 + chunk]);
        float4 v1 = __ldg(&sin[(size_t)c1 * 8 + chunk]);
        add8(acc, v0);
        add8(acc, v1);
    }
    // tail: up to 7 edges, 4 per iteration with validity masking
    for (; e < end; e += 4) {
        int idx = e + g;
        bool valid = idx < end;
        int c = valid ? __ldcs(&g_col[idx]) : r;
        float4 v = __ldg(&sin[(size_t)c * 8 + chunk]);
        if (valid) add8(acc, v);
    }

    // reduce across the 4 lane groups (lanes {l, l^8, l^16, l^24})
    #pragma unroll
    for (int i = 0; i < 8; i++) {
        acc[i] += __shfl_xor_sync(0xffffffffu, acc[i], 8);
        acc[i] += __shfl_xor_sync(0xffffffffu, acc[i], 16);
    }

    float outv[8];
    #pragma unroll
    for (int i = 0; i < 8; i++) outv[i] = dr * acc[i];

    // split epilogue stores across lane groups (no redundant traffic)
    if (g == 0) {
        float4* dst = (float4*)(o1 + (size_t)r * s1 + chunk * 8);
        __stcs(dst,     make_float4(outv[0], outv[1], outv[2], outv[3]));
        __stcs(dst + 1, make_float4(outv[4], outv[5], outv[6], outv[7]));
    } else if (g == 1 && o2) {
        float4* dst = (float4*)(o2 + (size_t)r * s2 + chunk * 8);
        __stcs(dst,     make_float4(outv[0], outv[1], outv[2], outv[3]));
        __stcs(dst + 1, make_float4(outv[4], outv[5], outv[6], outv[7]));
    } else if (g == 2 && sout) {
        float dr2 = dr * dr;
        float4 packed;
        __half2* h = (__half2*)&packed;
        h[0] = __floats2half2_rn(dr2 * acc[0], dr2 * acc[1]);
        h[1] = __floats2half2_rn(dr2 * acc[2], dr2 * acc[3]);
        h[2] = __floats2half2_rn(dr2 * acc[4], dr2 * acc[5]);
        h[3] = __floats2half2_rn(dr2 * acc[6], dr2 * acc[7]);
        sout[(size_t)r * 8 + chunk] = packed;   // gathered next layer: keep in L2
    }
}

extern "C" void kernel_launch(void* const* d_in, const int* in_sizes, int n_in,
                              void* d_out, int out_size) {
    const int*   edge = (const int*)d_in[0];    // [2, NEDGES] int32
    const float* emb  = (const float*)d_in[1];  // [NNODES, 64] f32
    float* out = (float*)d_out;                 // [N*3*64] all_feat + [N*64] final

    float4 *sA, *sB;
    cudaGetSymbolAddress((void**)&sA, g_sA);
    cudaGetSymbolAddress((void**)&sB, g_sB);

    const int T = 256;
    // ---- CSR build ----
    k_zero_deg<<<(NNODES + T - 1) / T, T>>>();
    k_count<<<(NEDGES + T - 1) / T, T>>>(edge);
    k_scan1<<<NSCANB, SCAN_B>>>();
    k_scan2<<<1, 256>>>();
    k_scan3<<<NSCANB, SCAN_B>>>();
    k_fill<<<(NEDGES + T - 1) / T, T>>>(edge);
    k_scale_emb<<<(NNODES * 8 + T - 1) / T, T>>>(emb);

    // ---- 3 propagation layers ----
    // all_feat perm (2,0,1): out[:,0,:]=L3, out[:,1,:]=L1, out[:,2,:]=L2; then final=L3
    int spmm_blocks = (NNODES * 32 + T - 1) / T;
    float* out_final = out + (size_t)NNODES * 3 * DIM;

    k_spmm<<<spmm_blocks, T>>>(sA, sB, out + DIM,     3 * DIM, nullptr,  0);       // L1
    k_spmm<<<spmm_blocks, T>>>(sB, sA, out + 2 * DIM, 3 * DIM, nullptr,  0);       // L2
    k_spmm<<<spmm_blocks, T>>>(sA, nullptr, out,      3 * DIM, out_final, DIM);    // L3
}